// round 2
// baseline (speedup 1.0000x reference)
#include <cuda_runtime.h>
#include <math.h>

#define T_LEN   16
#define C_DIM   192
#define DIN     384
#define DSTATE  16
#define DTRANK  12
#define XP_OUT  44
#define HW      784
#define STRIDE  388     // padded [t][c] stride
#define TSTR    18      // padded [c][t] stride (even -> 8B aligned vector LDS)

typedef unsigned long long u64;

__device__ __forceinline__ u64 pack2(float a, float b) {
    u64 r; asm("mov.b64 %0, {%1,%2};" : "=l"(r) : "f"(a), "f"(b)); return r;
}
__device__ __forceinline__ void ffma2(u64& d, u64 a, u64 b) {
    asm("fma.rn.f32x2 %0, %1, %2, %0;" : "+l"(d) : "l"(a), "l"(b));
}
__device__ __forceinline__ float2 unpack2(u64 v) {
    float2 f; asm("mov.b64 {%0,%1}, %2;" : "=f"(f.x), "=f"(f.y) : "l"(v)); return f;
}
__device__ __forceinline__ float siluf(float v) {
    return __fdividef(v, 1.0f + __expf(-v));
}

__global__ __launch_bounds__(512, 1)
void mamba_fused_kernel(const float* __restrict__ x,
                        const float* __restrict__ norm_w,
                        const float* __restrict__ in_proj_w,   // (192, 768)
                        const float* __restrict__ conv_w,      // (384, 4)
                        const float* __restrict__ conv_b,      // (384,)
                        const float* __restrict__ x_proj_w,    // (384, 44)
                        const float* __restrict__ dt_proj_w,   // (12, 384)
                        const float* __restrict__ dt_proj_b,   // (384,)
                        const float* __restrict__ A_log,       // (384, 16)
                        const float* __restrict__ Dp,          // (384,)
                        const float* __restrict__ out_proj_w,  // (384, 192)
                        float* __restrict__ out)
{
    extern __shared__ float sm[];
    float* s_xn = sm;                         // [c][t] 192*18 = 3456
    float* s_u  = s_xn + C_DIM * TSTR;        // [t][c] 16*388 = 6208
    float* s_z  = s_u  + T_LEN * STRIDE;      // 6208
    float* s_uc = s_z  + T_LEN * STRIDE;      // 6208
    float* s_dt = s_uc + T_LEN * STRIDE;      // 6208
    float* s_yT = s_dt + T_LEN * STRIDE;      // [c][t] 384*18 = 6912
    float* s_db = s_yT + DIN * TSTR;          // 16*44 = 704
    // total 35904 floats = 143616 B

    const int tid  = threadIdx.x;
    const int lane = tid & 31;
    const int wid  = tid >> 5;

    const int n  = blockIdx.x;
    const int b  = n / HW;
    const int hw = n - b * HW;
    const size_t tstride = (size_t)HW * C_DIM;
    const size_t base0   = ((size_t)b * T_LEN * HW + hw) * C_DIM;

    // ---------------- Phase A: load + RMSNorm -> s_xn[c][t] ----------------
    {
        const int t = wid;                      // 16 warps = 16 timesteps
        const float* row = x + base0 + (size_t)t * tstride;
        float v[6];
        float ss = 0.f;
        #pragma unroll
        for (int i = 0; i < 6; i++) { v[i] = row[lane + 32 * i]; ss = fmaf(v[i], v[i], ss); }
        #pragma unroll
        for (int o = 16; o; o >>= 1) ss += __shfl_xor_sync(0xffffffffu, ss, o);
        float nrm = rsqrtf(ss * (1.0f / 192.0f) + 1e-6f);
        #pragma unroll
        for (int i = 0; i < 6; i++) {
            int c = lane + 32 * i;
            s_xn[c * TSTR + t] = v[i] * nrm * norm_w[c];
        }
    }
    __syncthreads();

    // ---------------- Phase B: in_proj (16x192 @ 192x768) -> u, silu(z) ----
    // thread = (col in 0..255, t-half). Each thread: 3 cols x 8 timesteps.
    {
        const int col  = tid & 255;
        const int t0   = (tid >> 8) * 8;
        u64 acc0[4] = {0,0,0,0}, acc1[4] = {0,0,0,0}, acc2[4] = {0,0,0,0};
        #pragma unroll 2
        for (int k = 0; k < C_DIM; k++) {
            const float* wr = in_proj_w + k * 768;
            u64 w0 = pack2(wr[col],       wr[col]);
            u64 w1 = pack2(wr[col + 256], wr[col + 256]);
            u64 w2 = pack2(wr[col + 512], wr[col + 512]);
            const u64* xp = (const u64*)(s_xn + k * TSTR + t0);
            #pragma unroll
            for (int i = 0; i < 4; i++) {
                u64 xv = xp[i];
                ffma2(acc0[i], xv, w0);
                ffma2(acc1[i], xv, w1);
                ffma2(acc2[i], xv, w2);
            }
        }
        #pragma unroll
        for (int i = 0; i < 4; i++) {
            int t = t0 + 2 * i;
            float2 a0 = unpack2(acc0[i]);
            s_u[t * STRIDE + col]       = a0.x;
            s_u[(t + 1) * STRIDE + col] = a0.y;
            float2 a1 = unpack2(acc1[i]);
            if (col < 128) {
                s_u[t * STRIDE + col + 256]       = a1.x;
                s_u[(t + 1) * STRIDE + col + 256] = a1.y;
            } else {
                s_z[t * STRIDE + col - 128]       = siluf(a1.x);
                s_z[(t + 1) * STRIDE + col - 128] = siluf(a1.y);
            }
            float2 a2 = unpack2(acc2[i]);
            s_z[t * STRIDE + col + 128]       = siluf(a2.x);
            s_z[(t + 1) * STRIDE + col + 128] = siluf(a2.y);
        }
    }
    __syncthreads();

    // ---------------- Phase C: causal depthwise conv + silu -> s_uc --------
    for (int idx = tid; idx < T_LEN * DIN; idx += 512) {
        int t = idx / DIN;
        int c = idx - t * DIN;
        float4 cw = *(const float4*)(conv_w + c * 4);
        float acc = conv_b[c];
        if (t >= 3) {
            acc = fmaf(s_u[(t-3) * STRIDE + c], cw.x, acc);
            acc = fmaf(s_u[(t-2) * STRIDE + c], cw.y, acc);
            acc = fmaf(s_u[(t-1) * STRIDE + c], cw.z, acc);
        } else {
            if (t >= 1) acc = fmaf(s_u[(t-1) * STRIDE + c], cw.z, acc);
            if (t >= 2) acc = fmaf(s_u[(t-2) * STRIDE + c], cw.y, acc);
        }
        acc = fmaf(s_u[t * STRIDE + c], cw.w, acc);
        s_uc[t * STRIDE + c] = siluf(acc);
    }
    __syncthreads();

    // ---------------- Phase D: x_proj (16x384 @ 384x44) -> s_db ------------
    for (int o = tid; o < T_LEN * XP_OUT; o += 512) {
        int j = o >> 4;
        int t = o & 15;
        const float* ucr = s_uc + t * STRIDE;
        float acc = 0.f;
        for (int k = 0; k < DIN; k += 4) {
            float4 uv = *(const float4*)(ucr + k);
            acc = fmaf(uv.x, x_proj_w[(k + 0) * XP_OUT + j], acc);
            acc = fmaf(uv.y, x_proj_w[(k + 1) * XP_OUT + j], acc);
            acc = fmaf(uv.z, x_proj_w[(k + 2) * XP_OUT + j], acc);
            acc = fmaf(uv.w, x_proj_w[(k + 3) * XP_OUT + j], acc);
        }
        s_db[t * XP_OUT + j] = acc;
    }
    __syncthreads();

    // ---------------- Phase E: dt_proj + softplus -> s_dt ------------------
    for (int o = tid; o < T_LEN * DIN; o += 512) {
        int t = o / DIN;
        int c = o - t * DIN;
        float acc = dt_proj_b[c];
        const float* dr = s_db + t * XP_OUT;
        #pragma unroll
        for (int r = 0; r < DTRANK; r++)
            acc = fmaf(dr[r], dt_proj_w[r * DIN + c], acc);
        float sp = (acc > 20.f) ? acc : log1pf(__expf(acc));
        s_dt[t * STRIDE + c] = sp;
    }
    __syncthreads();

    // ---------------- Phase F: selective scan -> s_yT[c][t] ----------------
    if (tid < DIN) {
        const int c = tid;
        float A[DSTATE];
        {
            const float4* Ap = (const float4*)(A_log + c * DSTATE);
            #pragma unroll
            for (int q = 0; q < 4; q++) {
                float4 av = Ap[q];
                A[4*q+0] = -__expf(av.x); A[4*q+1] = -__expf(av.y);
                A[4*q+2] = -__expf(av.z); A[4*q+3] = -__expf(av.w);
            }
        }
        float h[DSTATE];
        #pragma unroll
        for (int s = 0; s < DSTATE; s++) h[s] = 0.f;
        const float Dc = Dp[c];

        #pragma unroll 1
        for (int t = 0; t < T_LEN; t++) {
            float dtv = s_dt[t * STRIDE + c];
            float ucv = s_uc[t * STRIDE + c];
            float du  = dtv * ucv;
            const float4* B4 = (const float4*)(s_db + t * XP_OUT + DTRANK);
            const float4* C4 = (const float4*)(s_db + t * XP_OUT + DTRANK + DSTATE);
            float y = 0.f;
            #pragma unroll
            for (int q = 0; q < 4; q++) {
                float4 Bv = B4[q];
                float4 Cv = C4[q];
                float dA, hb;
                dA = __expf(dtv * A[4*q+0]); hb = fmaf(h[4*q+0], dA, du * Bv.x); h[4*q+0] = hb; y = fmaf(hb, Cv.x, y);
                dA = __expf(dtv * A[4*q+1]); hb = fmaf(h[4*q+1], dA, du * Bv.y); h[4*q+1] = hb; y = fmaf(hb, Cv.y, y);
                dA = __expf(dtv * A[4*q+2]); hb = fmaf(h[4*q+2], dA, du * Bv.z); h[4*q+2] = hb; y = fmaf(hb, Cv.z, y);
                dA = __expf(dtv * A[4*q+3]); hb = fmaf(h[4*q+3], dA, du * Bv.w); h[4*q+3] = hb; y = fmaf(hb, Cv.w, y);
            }
            y = fmaf(ucv, Dc, y);
            s_yT[c * TSTR + t] = y * s_z[t * STRIDE + c];
        }
    }
    __syncthreads();

    // ---------------- Phase G: out_proj (16x384 @ 384x192) + residual ------
    if (tid < 2 * C_DIM) {
        int c = tid, half = 0;
        if (c >= C_DIM) { c -= C_DIM; half = 1; }
        const int t0 = half * 8;
        u64 acc[4] = {0,0,0,0};
        #pragma unroll 2
        for (int k = 0; k < DIN; k++) {
            float w = out_proj_w[k * C_DIM + c];
            u64 wp = pack2(w, w);
            const u64* yp = (const u64*)(s_yT + k * TSTR + t0);
            #pragma unroll
            for (int i = 0; i < 4; i++) ffma2(acc[i], yp[i], wp);
        }
        #pragma unroll
        for (int i = 0; i < 4; i++) {
            int t = t0 + 2 * i;
            float2 a = unpack2(acc[i]);
            size_t g0 = base0 + (size_t)t * tstride + c;
            size_t g1 = base0 + (size_t)(t + 1) * tstride + c;
            out[g0] = x[g0] + a.x;
            out[g1] = x[g1] + a.y;
        }
    }
}

extern "C" void kernel_launch(void* const* d_in, const int* in_sizes, int n_in,
                              void* d_out, int out_size)
{
    (void)in_sizes; (void)n_in; (void)out_size;
    const float* x         = (const float*)d_in[0];
    const float* norm_w    = (const float*)d_in[1];
    const float* in_proj_w = (const float*)d_in[2];
    const float* conv_w    = (const float*)d_in[3];
    const float* conv_b    = (const float*)d_in[4];
    const float* x_proj_w  = (const float*)d_in[5];
    const float* dt_proj_w = (const float*)d_in[6];
    const float* dt_proj_b = (const float*)d_in[7];
    const float* A_log     = (const float*)d_in[8];
    const float* Dp        = (const float*)d_in[9];
    const float* out_pw    = (const float*)d_in[10];
    float* out = (float*)d_out;

    const int smem_bytes = (C_DIM * TSTR + 4 * T_LEN * STRIDE + DIN * TSTR + T_LEN * XP_OUT)
                           * (int)sizeof(float);   // 143616
    cudaFuncSetAttribute(mamba_fused_kernel,
                         cudaFuncAttributeMaxDynamicSharedMemorySize, smem_bytes);

    dim3 grid(2 * HW);
    dim3 block(512);
    mamba_fused_kernel<<<grid, block, smem_bytes>>>(
        x, norm_w, in_proj_w, conv_w, conv_b, x_proj_w,
        dt_proj_w, dt_proj_b, A_log, Dp, out_pw, out);
}